// round 1
// baseline (speedup 1.0000x reference)
#include <cuda_runtime.h>
#include <mma.h>

using namespace nvcuda;

#define NEMBD 1024
#define TT 128
#define HS 128
#define NB 256

// Scratch for q, k, v (post-projection, post-RoPE). Device globals (no alloc).
__device__ float g_q[(size_t)NB * TT * HS];
__device__ float g_k[(size_t)NB * TT * HS];
__device__ float g_v[(size_t)NB * TT * HS];

static constexpr int AS_LD = 36;   // 128 x 36 fp32 (padded)
static constexpr int BS_LD = 132;  // 32 x 132 fp32 (padded)

// ---------------------------------------------------------------------------
// Kernel 1: C[128,128] = X[128,1024] @ W[1024,128] per (batch, weight) CTA,
// tf32 wmma, then RoPE for q/k (scale 1/sqrt(128) folded into q).
// ---------------------------------------------------------------------------
__global__ void qkv_rope_kernel(const float* __restrict__ x,
                                const float* __restrict__ Wq,
                                const float* __restrict__ Wk,
                                const float* __restrict__ Wv)
{
    extern __shared__ float smem[];
    float* As = smem;                  // [128][AS_LD]
    float* Bs = smem + 128 * AS_LD;    // [32][BS_LD]
    float* Cs = smem;                  // [128][128] (reused after K loop)

    const int b = blockIdx.x;   // batch == row tile (rows b*128 .. b*128+127)
    const int w = blockIdx.y;   // 0=q, 1=k, 2=v
    const float* W  = (w == 0) ? Wq : (w == 1) ? Wk : Wv;
    float*       Og = (w == 0) ? g_q : (w == 1) ? g_k : g_v;

    const int tid  = threadIdx.x;
    const int warp = tid >> 5;
    const int wm   = warp >> 1;    // 0..3  (32-row band)
    const int wn   = warp & 1;     // 0..1  (64-col band)

    wmma::fragment<wmma::accumulator, 16, 16, 8, float> acc[2][4];
    #pragma unroll
    for (int i = 0; i < 2; i++)
        #pragma unroll
        for (int j = 0; j < 4; j++)
            wmma::fill_fragment(acc[i][j], 0.0f);

    const float* xrow = x + (size_t)b * TT * NEMBD;

    for (int k0 = 0; k0 < NEMBD; k0 += 32) {
        // As: 128 x 32 (1024 float4), convert to tf32 on store
        #pragma unroll
        for (int i = tid; i < 1024; i += 256) {
            int r = i >> 3, c4 = i & 7;
            float4 v4 = *reinterpret_cast<const float4*>(xrow + (size_t)r * NEMBD + k0 + c4 * 4);
            float* dst = As + r * AS_LD + c4 * 4;
            dst[0] = wmma::__float_to_tf32(v4.x);
            dst[1] = wmma::__float_to_tf32(v4.y);
            dst[2] = wmma::__float_to_tf32(v4.z);
            dst[3] = wmma::__float_to_tf32(v4.w);
        }
        // Bs: 32 x 128 (1024 float4)
        #pragma unroll
        for (int i = tid; i < 1024; i += 256) {
            int r = i >> 5, c4 = i & 31;
            float4 v4 = *reinterpret_cast<const float4*>(W + (size_t)(k0 + r) * HS + c4 * 4);
            float* dst = Bs + r * BS_LD + c4 * 4;
            dst[0] = wmma::__float_to_tf32(v4.x);
            dst[1] = wmma::__float_to_tf32(v4.y);
            dst[2] = wmma::__float_to_tf32(v4.z);
            dst[3] = wmma::__float_to_tf32(v4.w);
        }
        __syncthreads();

        #pragma unroll
        for (int kk = 0; kk < 32; kk += 8) {
            wmma::fragment<wmma::matrix_a, 16, 16, 8, wmma::precision::tf32, wmma::row_major> af[2];
            wmma::fragment<wmma::matrix_b, 16, 16, 8, wmma::precision::tf32, wmma::row_major> bf[4];
            #pragma unroll
            for (int i = 0; i < 2; i++)
                wmma::load_matrix_sync(af[i], As + (wm * 32 + i * 16) * AS_LD + kk, AS_LD);
            #pragma unroll
            for (int j = 0; j < 4; j++)
                wmma::load_matrix_sync(bf[j], Bs + kk * BS_LD + wn * 64 + j * 16, BS_LD);
            #pragma unroll
            for (int i = 0; i < 2; i++)
                #pragma unroll
                for (int j = 0; j < 4; j++)
                    wmma::mma_sync(acc[i][j], af[i], bf[j], acc[i][j]);
        }
        __syncthreads();
    }

    // Park C in smem for RoPE / store
    #pragma unroll
    for (int i = 0; i < 2; i++)
        #pragma unroll
        for (int j = 0; j < 4; j++)
            wmma::store_matrix_sync(Cs + (wm * 32 + i * 16) * HS + wn * 64 + j * 16,
                                    acc[i][j], HS, wmma::mem_row_major);
    __syncthreads();

    float* outb = Og + (size_t)b * TT * HS;
    if (w == 2) {
        // v: straight copy
        for (int i = tid; i < (TT * HS) / 4; i += 256)
            reinterpret_cast<float4*>(outb)[i] = reinterpret_cast<const float4*>(Cs)[i];
    } else {
        const float qscale = (w == 0) ? 0.08838834764831845f : 1.0f; // 1/sqrt(128) folded into q
        const float nlt = -logf(10000.0f) * (2.0f / 128.0f);
        for (int i = tid; i < TT * 64; i += 256) {   // pair index
            int t = i >> 6;
            int p = i & 63;
            float inv_freq = expf(nlt * (float)p);
            float ang = (float)t * inv_freq;
            float s, c;
            sincosf(ang, &s, &c);
            float cr = Cs[t * HS + 2 * p];
            float ci = Cs[t * HS + 2 * p + 1];
            outb[t * HS + 2 * p]     = (cr * c - ci * s) * qscale;
            outb[t * HS + 2 * p + 1] = (cr * s + ci * c) * qscale;
        }
    }
}

// ---------------------------------------------------------------------------
// Kernel 2: per-batch attention. q,k,v tiles in smem (tf32), S = q k^T via
// wmma, causal softmax in smem (S overwrites q region), O = P v via wmma.
// ---------------------------------------------------------------------------
__global__ void attn_kernel(float* __restrict__ out)
{
    extern __shared__ float smem[];
    float* sq = smem;            // [128][128], later S/P
    float* sk = smem + 16384;    // [128][128]
    float* sv = smem + 32768;    // [128][128]

    const int b    = blockIdx.x;
    const int tid  = threadIdx.x;
    const int warp = tid >> 5;
    const int wm   = warp >> 1;
    const int wn   = warp & 1;

    const float* gq = g_q + (size_t)b * TT * HS;
    const float* gk = g_k + (size_t)b * TT * HS;
    const float* gv = g_v + (size_t)b * TT * HS;

    for (int i = tid; i < 4096; i += 256) {
        float4 a = reinterpret_cast<const float4*>(gq)[i];
        float4 c = reinterpret_cast<const float4*>(gk)[i];
        float4 d = reinterpret_cast<const float4*>(gv)[i];
        float* pq = sq + i * 4;
        float* pk = sk + i * 4;
        float* pv = sv + i * 4;
        pq[0] = wmma::__float_to_tf32(a.x); pq[1] = wmma::__float_to_tf32(a.y);
        pq[2] = wmma::__float_to_tf32(a.z); pq[3] = wmma::__float_to_tf32(a.w);
        pk[0] = wmma::__float_to_tf32(c.x); pk[1] = wmma::__float_to_tf32(c.y);
        pk[2] = wmma::__float_to_tf32(c.z); pk[3] = wmma::__float_to_tf32(c.w);
        pv[0] = wmma::__float_to_tf32(d.x); pv[1] = wmma::__float_to_tf32(d.y);
        pv[2] = wmma::__float_to_tf32(d.z); pv[3] = wmma::__float_to_tf32(d.w);
    }
    __syncthreads();

    // S = q @ k^T  (k as col-major B: B[d][s] = sk[s*128 + d])
    wmma::fragment<wmma::accumulator, 16, 16, 8, float> acc[2][4];
    #pragma unroll
    for (int i = 0; i < 2; i++)
        #pragma unroll
        for (int j = 0; j < 4; j++)
            wmma::fill_fragment(acc[i][j], 0.0f);

    #pragma unroll
    for (int kk = 0; kk < HS; kk += 8) {
        wmma::fragment<wmma::matrix_a, 16, 16, 8, wmma::precision::tf32, wmma::row_major> af[2];
        wmma::fragment<wmma::matrix_b, 16, 16, 8, wmma::precision::tf32, wmma::col_major> bf[4];
        #pragma unroll
        for (int i = 0; i < 2; i++)
            wmma::load_matrix_sync(af[i], sq + (wm * 32 + i * 16) * HS + kk, HS);
        #pragma unroll
        for (int j = 0; j < 4; j++)
            wmma::load_matrix_sync(bf[j], sk + (wn * 64 + j * 16) * HS + kk, HS);
        #pragma unroll
        for (int i = 0; i < 2; i++)
            #pragma unroll
            for (int j = 0; j < 4; j++)
                wmma::mma_sync(acc[i][j], af[i], bf[j], acc[i][j]);
    }
    __syncthreads();   // all reads of sq finished before S overwrites it

    #pragma unroll
    for (int i = 0; i < 2; i++)
        #pragma unroll
        for (int j = 0; j < 4; j++)
            wmma::store_matrix_sync(sq + (wm * 32 + i * 16) * HS + wn * 64 + j * 16,
                                    acc[i][j], HS, wmma::mem_row_major);
    __syncthreads();

    // Causal softmax, one row per thread (tid < 128). Result converted to tf32.
    if (tid < TT) {
        const int t = tid;
        float* row = sq + t * HS;
        float m = row[0];
        for (int s = 1; s <= t; s++) m = fmaxf(m, row[s]);
        float sum = 0.0f;
        for (int s = 0; s <= t; s++) {
            float e = expf(row[s] - m);
            sum += e;
            row[s] = e;
        }
        float inv = 1.0f / sum;
        for (int s = 0; s <= t; s++) row[s] = wmma::__float_to_tf32(row[s] * inv);
        for (int s = t + 1; s < TT; s++) row[s] = 0.0f;
    }
    __syncthreads();

    // O = P @ v
    #pragma unroll
    for (int i = 0; i < 2; i++)
        #pragma unroll
        for (int j = 0; j < 4; j++)
            wmma::fill_fragment(acc[i][j], 0.0f);

    #pragma unroll
    for (int kk = 0; kk < TT; kk += 8) {
        wmma::fragment<wmma::matrix_a, 16, 16, 8, wmma::precision::tf32, wmma::row_major> af[2];
        wmma::fragment<wmma::matrix_b, 16, 16, 8, wmma::precision::tf32, wmma::row_major> bf[4];
        #pragma unroll
        for (int i = 0; i < 2; i++)
            wmma::load_matrix_sync(af[i], sq + (wm * 32 + i * 16) * HS + kk, HS);
        #pragma unroll
        for (int j = 0; j < 4; j++)
            wmma::load_matrix_sync(bf[j], sv + kk * HS + wn * 64 + j * 16, HS);
        #pragma unroll
        for (int i = 0; i < 2; i++)
            #pragma unroll
            for (int j = 0; j < 4; j++)
                wmma::mma_sync(acc[i][j], af[i], bf[j], acc[i][j]);
    }

    float* ob = out + (size_t)b * TT * HS;
    #pragma unroll
    for (int i = 0; i < 2; i++)
        #pragma unroll
        for (int j = 0; j < 4; j++)
            wmma::store_matrix_sync(ob + (wm * 32 + i * 16) * HS + wn * 64 + j * 16,
                                    acc[i][j], HS, wmma::mem_row_major);
}

// ---------------------------------------------------------------------------
extern "C" void kernel_launch(void* const* d_in, const int* in_sizes, int n_in,
                              void* d_out, int out_size)
{
    const float* x  = (const float*)d_in[0];
    const float* Wq = (const float*)d_in[1];
    const float* Wk = (const float*)d_in[2];
    const float* Wv = (const float*)d_in[3];
    float* out = (float*)d_out;

    const int smem1 = 128 * 128 * sizeof(float);            // 64 KB (C reuse dominates)
    const int smem2 = 3 * 128 * 128 * sizeof(float);        // 192 KB

    cudaFuncSetAttribute(qkv_rope_kernel, cudaFuncAttributeMaxDynamicSharedMemorySize, smem1);
    cudaFuncSetAttribute(attn_kernel,     cudaFuncAttributeMaxDynamicSharedMemorySize, smem2);

    qkv_rope_kernel<<<dim3(NB, 3), 256, smem1>>>(x, Wq, Wk, Wv);
    attn_kernel<<<NB, 256, smem2>>>(out);
}

// round 3
// speedup vs baseline: 2.2767x; 2.2767x over previous
#include <cuda_runtime.h>
#include <cstdint>
#include <mma.h>

using namespace nvcuda;

#define NEMBD 1024
#define TT 128
#define HS 128
#define NB 256

// Scratch (device globals; no allocations allowed).
__device__ float g_q[(size_t)NB * TT * HS];
__device__ float g_k[(size_t)NB * TT * HS];
__device__ float g_v[(size_t)NB * TT * HS];
__device__ float g_xc[(size_t)NB * TT * NEMBD];   // x, RN-rounded to tf32
__device__ float g_wc[(size_t)3 * NEMBD * HS];    // Wq|Wk|Wv, RN-rounded to tf32

// ---------------------------------------------------------------------------
// Pre-pass: RN-round fp32 -> tf32 (stored as fp32, low mantissa zeroed).
// cp.async copies raw bits and HMMA-TF32 truncates; RN here keeps rel_err
// at the ~5e-4 level measured in R1. Device globals referenced directly —
// no cudaGetSymbolAddress on the host.
// ---------------------------------------------------------------------------
__global__ void conv_x_kernel(const float* __restrict__ src)
{
    const int n4 = NB * TT * NEMBD / 4;
    int stride = gridDim.x * blockDim.x;
    for (int i = blockIdx.x * blockDim.x + threadIdx.x; i < n4; i += stride) {
        float4 v = reinterpret_cast<const float4*>(src)[i];
        v.x = wmma::__float_to_tf32(v.x);
        v.y = wmma::__float_to_tf32(v.y);
        v.z = wmma::__float_to_tf32(v.z);
        v.w = wmma::__float_to_tf32(v.w);
        reinterpret_cast<float4*>(g_xc)[i] = v;
    }
}

__global__ void conv_w_kernel(const float* __restrict__ wq,
                              const float* __restrict__ wk,
                              const float* __restrict__ wv)
{
    const int n4 = NEMBD * HS / 4;   // per weight
    int stride = gridDim.x * blockDim.x;
    for (int i = blockIdx.x * blockDim.x + threadIdx.x; i < 3 * n4; i += stride) {
        int w = i / n4, j = i % n4;
        const float* src = (w == 0) ? wq : (w == 1) ? wk : wv;
        float4 v = reinterpret_cast<const float4*>(src)[j];
        v.x = wmma::__float_to_tf32(v.x);
        v.y = wmma::__float_to_tf32(v.y);
        v.z = wmma::__float_to_tf32(v.z);
        v.w = wmma::__float_to_tf32(v.w);
        reinterpret_cast<float4*>(g_wc)[i] = v;
    }
}

// ---------------------------------------------------------------------------
// QKV GEMM + RoPE. Grid (256 batches, 4 column-quarters of the 384-wide
// q|k|v output). 256 threads, 8 warps (4 row x 2 col), warp tile 32x48.
// 2-stage cp.async pipeline over K in chunks of 32.
// ---------------------------------------------------------------------------
static constexpr int AS_LD = 40;    // 128 x 40
static constexpr int BS_LD = 104;   // 32 x 104 (96 data cols)
static constexpr int CS_LD = 100;   // 128 x 100 (96 data cols)
static constexpr int STAGE_FLOATS = 128 * AS_LD + 32 * BS_LD;  // 8448

__device__ __forceinline__ void cp_async16(uint32_t saddr, const float* gptr)
{
    asm volatile("cp.async.cg.shared.global [%0], [%1], 16;\n"
                 :: "r"(saddr), "l"(gptr));
}

__global__ void __launch_bounds__(256)
qkv_rope_kernel()
{
    extern __shared__ float smem[];
    const int b       = blockIdx.x;
    const int quarter = blockIdx.y;           // 96-col slice of [0,384)
    const int tid     = threadIdx.x;
    const int warp    = tid >> 5;
    const int wm      = warp >> 1;            // 0..3
    const int wn      = warp & 1;             // 0..1

    const float* xrow = g_xc + (size_t)b * TT * NEMBD;

    wmma::fragment<wmma::accumulator, 16, 16, 8, float> acc[2][3];
    #pragma unroll
    for (int i = 0; i < 2; i++)
        #pragma unroll
        for (int j = 0; j < 3; j++)
            wmma::fill_fragment(acc[i][j], 0.0f);

    auto load_stage = [&](int buf, int k0) {
        float* As = smem + buf * STAGE_FLOATS;
        float* Bs = As + 128 * AS_LD;
        // A: 128 x 32 = 1024 float4
        #pragma unroll
        for (int j = 0; j < 4; j++) {
            int idx = tid + j * 256;
            int r = idx >> 3, c4 = idx & 7;
            uint32_t sa = (uint32_t)__cvta_generic_to_shared(As + r * AS_LD + c4 * 4);
            cp_async16(sa, xrow + (size_t)r * NEMBD + k0 + c4 * 4);
        }
        // B: 32 x 24 float4 = 768 float4 (96 cols of the q|k|v concat)
        #pragma unroll
        for (int j = 0; j < 3; j++) {
            int idx = tid + j * 256;
            int r = idx / 24, c4 = idx % 24;
            int colg4 = quarter * 24 + c4;          // global float4 col in [0,96)
            int w     = colg4 >> 5;
            int wc4   = colg4 & 31;
            uint32_t sa = (uint32_t)__cvta_generic_to_shared(Bs + r * BS_LD + c4 * 4);
            cp_async16(sa, g_wc + (size_t)w * NEMBD * HS + (size_t)(k0 + r) * HS + wc4 * 4);
        }
    };

    load_stage(0, 0);
    asm volatile("cp.async.commit_group;\n");
    load_stage(1, 32);
    asm volatile("cp.async.commit_group;\n");

    for (int it = 0; it < 32; ++it) {
        asm volatile("cp.async.wait_group 1;\n");
        __syncthreads();

        const float* As = smem + (it & 1) * STAGE_FLOATS;
        const float* Bs = As + 128 * AS_LD;

        #pragma unroll
        for (int kk = 0; kk < 32; kk += 8) {
            wmma::fragment<wmma::matrix_a, 16, 16, 8, wmma::precision::tf32, wmma::row_major> af[2];
            wmma::fragment<wmma::matrix_b, 16, 16, 8, wmma::precision::tf32, wmma::row_major> bf[3];
            #pragma unroll
            for (int i = 0; i < 2; i++)
                wmma::load_matrix_sync(af[i], As + (wm * 32 + i * 16) * AS_LD + kk, AS_LD);
            #pragma unroll
            for (int j = 0; j < 3; j++)
                wmma::load_matrix_sync(bf[j], Bs + kk * BS_LD + wn * 48 + j * 16, BS_LD);
            #pragma unroll
            for (int i = 0; i < 2; i++)
                #pragma unroll
                for (int j = 0; j < 3; j++)
                    wmma::mma_sync(acc[i][j], af[i], bf[j], acc[i][j]);
        }
        __syncthreads();

        if (it + 2 < 32) load_stage(it & 1, (it + 2) * 32);
        asm volatile("cp.async.commit_group;\n");
    }

    asm volatile("cp.async.wait_group 0;\n");
    __syncthreads();

    // Park C tile (128 x 96) in smem (reuse pipeline buffers).
    float* Cs = smem;
    #pragma unroll
    for (int i = 0; i < 2; i++)
        #pragma unroll
        for (int j = 0; j < 3; j++)
            wmma::store_matrix_sync(Cs + (wm * 32 + i * 16) * CS_LD + wn * 48 + j * 16,
                                    acc[i][j], CS_LD, wmma::mem_row_major);
    __syncthreads();

    // Epilogue: RoPE for q/k sections, raw copy for v. 128 rows x 48 pairs.
    const float nlt = -logf(10000.0f) * (2.0f / 128.0f);
    for (int idx = tid; idx < TT * 48; idx += 256) {
        int t  = idx / 48;
        int pp = idx % 48;
        int c  = 2 * pp;
        int colg = quarter * 96 + c;     // global col in [0,384)
        int w    = colg >> 7;            // 0=q 1=k 2=v
        int wc   = colg & 127;
        float cr = Cs[t * CS_LD + c];
        float ci = Cs[t * CS_LD + c + 1];
        float* outb;
        if (w == 0) outb = g_q + (size_t)b * TT * HS;
        else if (w == 1) outb = g_k + (size_t)b * TT * HS;
        else outb = g_v + (size_t)b * TT * HS;
        if (w == 2) {
            outb[t * HS + wc]     = cr;
            outb[t * HS + wc + 1] = ci;
        } else {
            int p = wc >> 1;
            float inv_freq = expf(nlt * (float)p);
            float ang = (float)t * inv_freq;
            float s, cc;
            sincosf(ang, &s, &cc);
            float qscale = (w == 0) ? 0.08838834764831845f : 1.0f;  // 1/sqrt(128)
            outb[t * HS + wc]     = (cr * cc - ci * s) * qscale;
            outb[t * HS + wc + 1] = (cr * s + ci * cc) * qscale;
        }
    }
}

// ---------------------------------------------------------------------------
// Kernel 2: per-batch attention (unchanged from R1 — 95.6us measured).
// ---------------------------------------------------------------------------
__global__ void attn_kernel(float* __restrict__ out)
{
    extern __shared__ float smem[];
    float* sq = smem;            // [128][128], later S/P
    float* sk = smem + 16384;
    float* sv = smem + 32768;

    const int b    = blockIdx.x;
    const int tid  = threadIdx.x;
    const int warp = tid >> 5;
    const int wm   = warp >> 1;
    const int wn   = warp & 1;

    const float* gq = g_q + (size_t)b * TT * HS;
    const float* gk = g_k + (size_t)b * TT * HS;
    const float* gv = g_v + (size_t)b * TT * HS;

    for (int i = tid; i < 4096; i += 256) {
        float4 a = reinterpret_cast<const float4*>(gq)[i];
        float4 c = reinterpret_cast<const float4*>(gk)[i];
        float4 d = reinterpret_cast<const float4*>(gv)[i];
        float* pq = sq + i * 4;
        float* pk = sk + i * 4;
        float* pv = sv + i * 4;
        pq[0] = wmma::__float_to_tf32(a.x); pq[1] = wmma::__float_to_tf32(a.y);
        pq[2] = wmma::__float_to_tf32(a.z); pq[3] = wmma::__float_to_tf32(a.w);
        pk[0] = wmma::__float_to_tf32(c.x); pk[1] = wmma::__float_to_tf32(c.y);
        pk[2] = wmma::__float_to_tf32(c.z); pk[3] = wmma::__float_to_tf32(c.w);
        pv[0] = wmma::__float_to_tf32(d.x); pv[1] = wmma::__float_to_tf32(d.y);
        pv[2] = wmma::__float_to_tf32(d.z); pv[3] = wmma::__float_to_tf32(d.w);
    }
    __syncthreads();

    wmma::fragment<wmma::accumulator, 16, 16, 8, float> acc[2][4];
    #pragma unroll
    for (int i = 0; i < 2; i++)
        #pragma unroll
        for (int j = 0; j < 4; j++)
            wmma::fill_fragment(acc[i][j], 0.0f);

    #pragma unroll
    for (int kk = 0; kk < HS; kk += 8) {
        wmma::fragment<wmma::matrix_a, 16, 16, 8, wmma::precision::tf32, wmma::row_major> af[2];
        wmma::fragment<wmma::matrix_b, 16, 16, 8, wmma::precision::tf32, wmma::col_major> bf[4];
        #pragma unroll
        for (int i = 0; i < 2; i++)
            wmma::load_matrix_sync(af[i], sq + (wm * 32 + i * 16) * HS + kk, HS);
        #pragma unroll
        for (int j = 0; j < 4; j++)
            wmma::load_matrix_sync(bf[j], sk + (wn * 64 + j * 16) * HS + kk, HS);
        #pragma unroll
        for (int i = 0; i < 2; i++)
            #pragma unroll
            for (int j = 0; j < 4; j++)
                wmma::mma_sync(acc[i][j], af[i], bf[j], acc[i][j]);
    }
    __syncthreads();

    #pragma unroll
    for (int i = 0; i < 2; i++)
        #pragma unroll
        for (int j = 0; j < 4; j++)
            wmma::store_matrix_sync(sq + (wm * 32 + i * 16) * HS + wn * 64 + j * 16,
                                    acc[i][j], HS, wmma::mem_row_major);
    __syncthreads();

    if (tid < TT) {
        const int t = tid;
        float* row = sq + t * HS;
        float m = row[0];
        for (int s = 1; s <= t; s++) m = fmaxf(m, row[s]);
        float sum = 0.0f;
        for (int s = 0; s <= t; s++) {
            float e = expf(row[s] - m);
            sum += e;
            row[s] = e;
        }
        float inv = 1.0f / sum;
        for (int s = 0; s <= t; s++) row[s] = wmma::__float_to_tf32(row[s] * inv);
        for (int s = t + 1; s < TT; s++) row[s] = 0.0f;
    }
    __syncthreads();

    #pragma unroll
    for (int i = 0; i < 2; i++)
        #pragma unroll
        for (int j = 0; j < 4; j++)
            wmma::fill_fragment(acc[i][j], 0.0f);

    #pragma unroll
    for (int kk = 0; kk < TT; kk += 8) {
        wmma::fragment<wmma::matrix_a, 16, 16, 8, wmma::precision::tf32, wmma::row_major> af[2];
        wmma::fragment<wmma::matrix_b, 16, 16, 8, wmma::precision::tf32, wmma::row_major> bf[4];
        #pragma unroll
        for (int i = 0; i < 2; i++)
            wmma::load_matrix_sync(af[i], sq + (wm * 32 + i * 16) * HS + kk, HS);
        #pragma unroll
        for (int j = 0; j < 4; j++)
            wmma::load_matrix_sync(bf[j], sv + kk * HS + wn * 64 + j * 16, HS);
        #pragma unroll
        for (int i = 0; i < 2; i++)
            #pragma unroll
            for (int j = 0; j < 4; j++)
                wmma::mma_sync(acc[i][j], af[i], bf[j], acc[i][j]);
    }

    float* ob = out + (size_t)b * TT * HS;
    #pragma unroll
    for (int i = 0; i < 2; i++)
        #pragma unroll
        for (int j = 0; j < 4; j++)
            wmma::store_matrix_sync(ob + (wm * 32 + i * 16) * HS + wn * 64 + j * 16,
                                    acc[i][j], HS, wmma::mem_row_major);
}

// ---------------------------------------------------------------------------
extern "C" void kernel_launch(void* const* d_in, const int* in_sizes, int n_in,
                              void* d_out, int out_size)
{
    const float* x  = (const float*)d_in[0];
    const float* Wq = (const float*)d_in[1];
    const float* Wk = (const float*)d_in[2];
    const float* Wv = (const float*)d_in[3];
    float* out = (float*)d_out;

    const int smem1 = 2 * STAGE_FLOATS * sizeof(float);   // 67.6 KB
    const int smem2 = 3 * 128 * 128 * sizeof(float);      // 192 KB

    cudaFuncSetAttribute(qkv_rope_kernel, cudaFuncAttributeMaxDynamicSharedMemorySize, smem1);
    cudaFuncSetAttribute(attn_kernel,     cudaFuncAttributeMaxDynamicSharedMemorySize, smem2);

    conv_x_kernel<<<1024, 256>>>(x);
    conv_w_kernel<<<96, 256>>>(Wq, Wk, Wv);

    qkv_rope_kernel<<<dim3(NB, 4), 256, smem1>>>();
    attn_kernel<<<NB, 256, smem2>>>(out);
}

// round 4
// speedup vs baseline: 2.3449x; 1.0299x over previous
#include <cuda_runtime.h>
#include <cstdint>
#include <mma.h>

using namespace nvcuda;

#define NEMBD 1024
#define TT 128
#define HS 128
#define NB 256

// Scratch (device globals; no allocations allowed).
__device__ float g_q[(size_t)NB * TT * HS];
__device__ float g_k[(size_t)NB * TT * HS];
__device__ float g_v[(size_t)NB * TT * HS];
__device__ float g_xc[(size_t)NB * TT * NEMBD];   // x, RN-rounded to tf32
__device__ float g_wc[(size_t)3 * NEMBD * HS];    // Wq|Wk|Wv, RN-rounded to tf32

// ---------------------------------------------------------------------------
// Pre-pass: RN-round fp32 -> tf32 (cp.async copies raw bits and HMMA-TF32
// truncates; RN keeps rel_err ~5e-4).
// ---------------------------------------------------------------------------
__global__ void conv_x_kernel(const float* __restrict__ src)
{
    const int n4 = NB * TT * NEMBD / 4;
    int stride = gridDim.x * blockDim.x;
    for (int i = blockIdx.x * blockDim.x + threadIdx.x; i < n4; i += stride) {
        float4 v = reinterpret_cast<const float4*>(src)[i];
        v.x = wmma::__float_to_tf32(v.x);
        v.y = wmma::__float_to_tf32(v.y);
        v.z = wmma::__float_to_tf32(v.z);
        v.w = wmma::__float_to_tf32(v.w);
        reinterpret_cast<float4*>(g_xc)[i] = v;
    }
}

__global__ void conv_w_kernel(const float* __restrict__ wq,
                              const float* __restrict__ wk,
                              const float* __restrict__ wv)
{
    const int n4 = NEMBD * HS / 4;   // per weight
    int stride = gridDim.x * blockDim.x;
    for (int i = blockIdx.x * blockDim.x + threadIdx.x; i < 3 * n4; i += stride) {
        int w = i / n4, j = i % n4;
        const float* src = (w == 0) ? wq : (w == 1) ? wk : wv;
        float4 v = reinterpret_cast<const float4*>(src)[j];
        v.x = wmma::__float_to_tf32(v.x);
        v.y = wmma::__float_to_tf32(v.y);
        v.z = wmma::__float_to_tf32(v.z);
        v.w = wmma::__float_to_tf32(v.w);
        reinterpret_cast<float4*>(g_wc)[i] = v;
    }
}

// ---------------------------------------------------------------------------
// QKV GEMM + RoPE. Grid (3 weights, 128 row-pairs). CTA tile: 256 rows
// (2 batches) x 128 cols. 8 warps as 4x2, warp tile 64x64 (16 acc frags).
// 4-buffer cp.async pipeline, 3 stages in flight, ONE syncthreads/iter.
// ---------------------------------------------------------------------------
static constexpr int AS_LD = 36;                      // 256 x 36
static constexpr int BS_LD = 132;                     // 32 x 132
static constexpr int A_FL  = 256 * AS_LD;             // 9216
static constexpr int B_FL  = 32 * BS_LD;              // 4224
static constexpr int ST_FL = A_FL + B_FL;             // 13440 floats / stage
static constexpr int NBUF  = 4;
static constexpr int QKV_SMEM = NBUF * ST_FL * 4;     // 215040 B

__device__ __forceinline__ void cp_async16(uint32_t saddr, const float* gptr)
{
    asm volatile("cp.async.cg.shared.global [%0], [%1], 16;\n"
                 :: "r"(saddr), "l"(gptr));
}

__global__ void __launch_bounds__(256)
qkv_rope_kernel()
{
    extern __shared__ float smem[];
    const int w    = blockIdx.x;          // 0=q 1=k 2=v
    const int b2   = blockIdx.y;          // row-pair: rows b2*256 .. +255
    const int tid  = threadIdx.x;
    const int warp = tid >> 5;
    const int wm   = warp >> 1;           // 0..3 -> 64-row band
    const int wn   = warp & 1;            // 0..1 -> 64-col band

    const float* xbase = g_xc + (size_t)b2 * 256 * NEMBD;
    const float* wbase = g_wc + (size_t)w * NEMBD * HS;

    wmma::fragment<wmma::accumulator, 16, 16, 8, float> acc[4][4];
    #pragma unroll
    for (int i = 0; i < 4; i++)
        #pragma unroll
        for (int j = 0; j < 4; j++)
            wmma::fill_fragment(acc[i][j], 0.0f);

    auto load_stage = [&](int stage) {      // stage index 0..31
        float* As = smem + (stage & 3) * ST_FL;
        float* Bs = As + A_FL;
        int k0 = stage * 32;
        // A: 256 x 32 floats = 2048 float4, 8 per thread
        #pragma unroll
        for (int j = 0; j < 8; j++) {
            int idx = tid + j * 256;
            int r = idx >> 3, c4 = idx & 7;
            uint32_t sa = (uint32_t)__cvta_generic_to_shared(As + r * AS_LD + c4 * 4);
            cp_async16(sa, xbase + (size_t)r * NEMBD + k0 + c4 * 4);
        }
        // B: 32 x 128 floats = 1024 float4, 4 per thread
        #pragma unroll
        for (int j = 0; j < 4; j++) {
            int idx = tid + j * 256;
            int r = idx >> 5, c4 = idx & 31;
            uint32_t sa = (uint32_t)__cvta_generic_to_shared(Bs + r * BS_LD + c4 * 4);
            cp_async16(sa, wbase + (size_t)(k0 + r) * HS + c4 * 4);
        }
    };

    load_stage(0); asm volatile("cp.async.commit_group;\n");
    load_stage(1); asm volatile("cp.async.commit_group;\n");
    load_stage(2); asm volatile("cp.async.commit_group;\n");

    for (int it = 0; it < 32; ++it) {
        asm volatile("cp.async.wait_group 2;\n");
        __syncthreads();

        const float* As = smem + (it & 3) * ST_FL;
        const float* Bs = As + A_FL;

        #pragma unroll
        for (int kk = 0; kk < 32; kk += 8) {
            wmma::fragment<wmma::matrix_a, 16, 16, 8, wmma::precision::tf32, wmma::row_major> af[4];
            wmma::fragment<wmma::matrix_b, 16, 16, 8, wmma::precision::tf32, wmma::row_major> bf[4];
            #pragma unroll
            for (int i = 0; i < 4; i++)
                wmma::load_matrix_sync(af[i], As + (wm * 64 + i * 16) * AS_LD + kk, AS_LD);
            #pragma unroll
            for (int j = 0; j < 4; j++)
                wmma::load_matrix_sync(bf[j], Bs + kk * BS_LD + wn * 64 + j * 16, BS_LD);
            #pragma unroll
            for (int i = 0; i < 4; i++)
                #pragma unroll
                for (int j = 0; j < 4; j++)
                    wmma::mma_sync(acc[i][j], af[i], bf[j], acc[i][j]);
        }

        if (it + 3 < 32) load_stage(it + 3);
        asm volatile("cp.async.commit_group;\n");   // empty group OK (keeps numbering)
    }

    asm volatile("cp.async.wait_group 0;\n");
    __syncthreads();

    // Park C (256 x 128) in smem (reuses pipeline buffers: 128KB <= 210KB).
    float* Cs = smem;
    #pragma unroll
    for (int i = 0; i < 4; i++)
        #pragma unroll
        for (int j = 0; j < 4; j++)
            wmma::store_matrix_sync(Cs + (wm * 64 + i * 16) * HS + wn * 64 + j * 16,
                                    acc[i][j], HS, wmma::mem_row_major);
    __syncthreads();

    float* outb = ((w == 0) ? g_q : (w == 1) ? g_k : g_v) + (size_t)b2 * 256 * HS;

    if (w == 2) {
        // v: straight copy, 8192 float4
        for (int i = tid; i < 256 * HS / 4; i += 256)
            reinterpret_cast<float4*>(outb)[i] = reinterpret_cast<const float4*>(Cs)[i];
    } else {
        const float qscale = (w == 0) ? 0.08838834764831845f : 1.0f;  // 1/sqrt(128)
        const float nlt = -logf(10000.0f) * (2.0f / 128.0f);
        for (int idx = tid; idx < 256 * 64; idx += 256) {   // pair index
            int r = idx >> 6;            // 0..255
            int p = idx & 63;
            int t = r & 127;             // position within sequence
            float inv_freq = __expf(nlt * (float)p);
            float ang = (float)t * inv_freq;
            float s, c;
            sincosf(ang, &s, &c);
            float cr = Cs[r * HS + 2 * p];
            float ci = Cs[r * HS + 2 * p + 1];
            outb[r * HS + 2 * p]     = (cr * c - ci * s) * qscale;
            outb[r * HS + 2 * p + 1] = (cr * s + ci * c) * qscale;
        }
    }
}

// ---------------------------------------------------------------------------
// Kernel 2: per-batch attention. Same structure as R1/R3 but softmax is now
// warp-parallel (warp per row, shfl reductions, __expf).
// ---------------------------------------------------------------------------
__global__ void attn_kernel(float* __restrict__ out)
{
    extern __shared__ float smem[];
    float* sq = smem;            // [128][128], later S/P
    float* sk = smem + 16384;
    float* sv = smem + 32768;

    const int b    = blockIdx.x;
    const int tid  = threadIdx.x;
    const int warp = tid >> 5;
    const int lane = tid & 31;
    const int wm   = warp >> 1;
    const int wn   = warp & 1;

    const float* gq = g_q + (size_t)b * TT * HS;
    const float* gk = g_k + (size_t)b * TT * HS;
    const float* gv = g_v + (size_t)b * TT * HS;

    for (int i = tid; i < 4096; i += 256) {
        float4 a = reinterpret_cast<const float4*>(gq)[i];
        float4 c = reinterpret_cast<const float4*>(gk)[i];
        float4 d = reinterpret_cast<const float4*>(gv)[i];
        float* pq = sq + i * 4;
        float* pk = sk + i * 4;
        float* pv = sv + i * 4;
        pq[0] = wmma::__float_to_tf32(a.x); pq[1] = wmma::__float_to_tf32(a.y);
        pq[2] = wmma::__float_to_tf32(a.z); pq[3] = wmma::__float_to_tf32(a.w);
        pk[0] = wmma::__float_to_tf32(c.x); pk[1] = wmma::__float_to_tf32(c.y);
        pk[2] = wmma::__float_to_tf32(c.z); pk[3] = wmma::__float_to_tf32(c.w);
        pv[0] = wmma::__float_to_tf32(d.x); pv[1] = wmma::__float_to_tf32(d.y);
        pv[2] = wmma::__float_to_tf32(d.z); pv[3] = wmma::__float_to_tf32(d.w);
    }
    __syncthreads();

    wmma::fragment<wmma::accumulator, 16, 16, 8, float> acc[2][4];
    #pragma unroll
    for (int i = 0; i < 2; i++)
        #pragma unroll
        for (int j = 0; j < 4; j++)
            wmma::fill_fragment(acc[i][j], 0.0f);

    #pragma unroll
    for (int kk = 0; kk < HS; kk += 8) {
        wmma::fragment<wmma::matrix_a, 16, 16, 8, wmma::precision::tf32, wmma::row_major> af[2];
        wmma::fragment<wmma::matrix_b, 16, 16, 8, wmma::precision::tf32, wmma::col_major> bf[4];
        #pragma unroll
        for (int i = 0; i < 2; i++)
            wmma::load_matrix_sync(af[i], sq + (wm * 32 + i * 16) * HS + kk, HS);
        #pragma unroll
        for (int j = 0; j < 4; j++)
            wmma::load_matrix_sync(bf[j], sk + (wn * 64 + j * 16) * HS + kk, HS);
        #pragma unroll
        for (int i = 0; i < 2; i++)
            #pragma unroll
            for (int j = 0; j < 4; j++)
                wmma::mma_sync(acc[i][j], af[i], bf[j], acc[i][j]);
    }
    __syncthreads();

    #pragma unroll
    for (int i = 0; i < 2; i++)
        #pragma unroll
        for (int j = 0; j < 4; j++)
            wmma::store_matrix_sync(sq + (wm * 32 + i * 16) * HS + wn * 64 + j * 16,
                                    acc[i][j], HS, wmma::mem_row_major);
    __syncthreads();

    // Warp-parallel causal softmax: warp handles rows warp*16 .. +15.
    // Each lane owns 4 columns (float4).
    #pragma unroll 1
    for (int rr = 0; rr < 16; rr++) {
        const int t = warp * 16 + rr;
        float4 v4 = reinterpret_cast<float4*>(sq + t * HS)[lane];
        const int c0 = lane * 4;

        float m = -1e30f;
        if (c0 + 0 <= t) m = fmaxf(m, v4.x);
        if (c0 + 1 <= t) m = fmaxf(m, v4.y);
        if (c0 + 2 <= t) m = fmaxf(m, v4.z);
        if (c0 + 3 <= t) m = fmaxf(m, v4.w);
        #pragma unroll
        for (int off = 16; off > 0; off >>= 1)
            m = fmaxf(m, __shfl_xor_sync(0xffffffffu, m, off));

        float e0 = (c0 + 0 <= t) ? __expf(v4.x - m) : 0.0f;
        float e1 = (c0 + 1 <= t) ? __expf(v4.y - m) : 0.0f;
        float e2 = (c0 + 2 <= t) ? __expf(v4.z - m) : 0.0f;
        float e3 = (c0 + 3 <= t) ? __expf(v4.w - m) : 0.0f;
        float s = e0 + e1 + e2 + e3;
        #pragma unroll
        for (int off = 16; off > 0; off >>= 1)
            s += __shfl_xor_sync(0xffffffffu, s, off);

        float inv = 1.0f / s;
        v4.x = wmma::__float_to_tf32(e0 * inv);
        v4.y = wmma::__float_to_tf32(e1 * inv);
        v4.z = wmma::__float_to_tf32(e2 * inv);
        v4.w = wmma::__float_to_tf32(e3 * inv);
        reinterpret_cast<float4*>(sq + t * HS)[lane] = v4;
    }
    __syncthreads();

    #pragma unroll
    for (int i = 0; i < 2; i++)
        #pragma unroll
        for (int j = 0; j < 4; j++)
            wmma::fill_fragment(acc[i][j], 0.0f);

    #pragma unroll
    for (int kk = 0; kk < TT; kk += 8) {
        wmma::fragment<wmma::matrix_a, 16, 16, 8, wmma::precision::tf32, wmma::row_major> af[2];
        wmma::fragment<wmma::matrix_b, 16, 16, 8, wmma::precision::tf32, wmma::row_major> bf[4];
        #pragma unroll
        for (int i = 0; i < 2; i++)
            wmma::load_matrix_sync(af[i], sq + (wm * 32 + i * 16) * HS + kk, HS);
        #pragma unroll
        for (int j = 0; j < 4; j++)
            wmma::load_matrix_sync(bf[j], sv + kk * HS + wn * 64 + j * 16, HS);
        #pragma unroll
        for (int i = 0; i < 2; i++)
            #pragma unroll
            for (int j = 0; j < 4; j++)
                wmma::mma_sync(acc[i][j], af[i], bf[j], acc[i][j]);
    }

    float* ob = out + (size_t)b * TT * HS;
    #pragma unroll
    for (int i = 0; i < 2; i++)
        #pragma unroll
        for (int j = 0; j < 4; j++)
            wmma::store_matrix_sync(ob + (wm * 32 + i * 16) * HS + wn * 64 + j * 16,
                                    acc[i][j], HS, wmma::mem_row_major);
}

// ---------------------------------------------------------------------------
extern "C" void kernel_launch(void* const* d_in, const int* in_sizes, int n_in,
                              void* d_out, int out_size)
{
    const float* x  = (const float*)d_in[0];
    const float* Wq = (const float*)d_in[1];
    const float* Wk = (const float*)d_in[2];
    const float* Wv = (const float*)d_in[3];
    float* out = (float*)d_out;

    const int smem2 = 3 * 128 * 128 * sizeof(float);      // 192 KB

    cudaFuncSetAttribute(qkv_rope_kernel, cudaFuncAttributeMaxDynamicSharedMemorySize, QKV_SMEM);
    cudaFuncSetAttribute(attn_kernel,     cudaFuncAttributeMaxDynamicSharedMemorySize, smem2);

    conv_x_kernel<<<1024, 256>>>(x);
    conv_w_kernel<<<96, 256>>>(Wq, Wk, Wv);

    qkv_rope_kernel<<<dim3(3, 128), 256, QKV_SMEM>>>();
    attn_kernel<<<NB, 256, smem2>>>(out);
}